// round 1
// baseline (speedup 1.0000x reference)
#include <cuda_runtime.h>
#include <math.h>

// ---------------- problem constants ----------------
#define Bb    64
#define Ss    1024
#define Dd    256
#define Hh    256
#define H2    512
#define Ff    128
#define Tt    64
#define Ll    8
#define NSEG  128
#define DIN   1152
#define G4    2048           // 4 * H2
#define NROWS 65536          // B * S
#define NSEGT 8192           // B * NSEG

// ---------------- scratch (static device, no allocs) ----------------
__device__ float g_decin[NSEGT * DIN];          // [8192,1152]
__device__ float g_U[(size_t)NROWS * 768];      // conv tap GEMM output
__device__ float g_Wall[768 * Dd];              // stacked conv weights [768,256]
__device__ float g_gx[(size_t)NSEGT * G4];      // gates_x = dec_in @ W_ih^T
__device__ float g_h[(size_t)129 * Bb * H2];    // h per step, slot 0 = h0
__device__ float g_logits[(size_t)NSEGT * Tt];
__device__ unsigned g_bar_count;
__device__ volatile unsigned g_bar_gen;

// ---------------- helpers ----------------
__device__ __forceinline__ unsigned f2tf(float x) {
    unsigned u;
    asm("cvt.rna.tf32.f32 %0, %1;" : "=r"(u) : "f"(x));
    return u;
}
__device__ __forceinline__ float sigmf(float x) { return 1.f / (1.f + __expf(-x)); }

// ---------------- tf32 GEMM: C[M,N] = A[M,K] @ B[N,K]^T ----------------
// gather != nullptr: A row m is A[gather[m]*K ...] (embedding lookup fused)
#define BM 64
#define BN 64
#define BK 32
#define SP 36   // smem pitch (uint32), conflict-free fragment loads

__global__ __launch_bounds__(256) void gemm_tf32(
    const float* __restrict__ A, const float* __restrict__ Bw,
    float* __restrict__ C, int M, int N, int K,
    const int* __restrict__ gather)
{
    __shared__ unsigned As[BM * SP];
    __shared__ unsigned Bs[BN * SP];
    __shared__ int rows_s[BM];

    int tid = threadIdx.x;
    int mBase = blockIdx.y * BM, nBase = blockIdx.x * BN;
    if (tid < BM) rows_s[tid] = gather ? gather[mBase + tid] : (mBase + tid);
    __syncthreads();

    int w = tid >> 5, lane = tid & 31;
    int wm = w & 3, wn = w >> 2;      // 4x2 warp grid: warp tile 16x32
    int grp = lane >> 2, tig = lane & 3;

    float acc[4][4];
#pragma unroll
    for (int i = 0; i < 4; i++)
#pragma unroll
        for (int j = 0; j < 4; j++) acc[i][j] = 0.f;

    int nkt = K / BK;
    for (int kt = 0; kt < nkt; kt++) {
#pragma unroll
        for (int it = 0; it < 2; it++) {          // A tile: 64x32
            int item = tid + it * 256;
            int row = item >> 3, c4 = (item & 7) * 4;
            float4 v = *(const float4*)(A + (size_t)rows_s[row] * K + kt * BK + c4);
            unsigned* d = &As[row * SP + c4];
            d[0] = f2tf(v.x); d[1] = f2tf(v.y); d[2] = f2tf(v.z); d[3] = f2tf(v.w);
        }
#pragma unroll
        for (int it = 0; it < 2; it++) {          // B tile: 64x32
            int item = tid + it * 256;
            int row = item >> 3, c4 = (item & 7) * 4;
            float4 v = *(const float4*)(Bw + (size_t)(nBase + row) * K + kt * BK + c4);
            unsigned* d = &Bs[row * SP + c4];
            d[0] = f2tf(v.x); d[1] = f2tf(v.y); d[2] = f2tf(v.z); d[3] = f2tf(v.w);
        }
        __syncthreads();

#pragma unroll
        for (int ks = 0; ks < 4; ks++) {
            int k0 = ks * 8;
            unsigned a0 = As[(wm * 16 + grp) * SP + k0 + tig];
            unsigned a1 = As[(wm * 16 + grp + 8) * SP + k0 + tig];
            unsigned a2 = As[(wm * 16 + grp) * SP + k0 + tig + 4];
            unsigned a3 = As[(wm * 16 + grp + 8) * SP + k0 + tig + 4];
#pragma unroll
            for (int nt = 0; nt < 4; nt++) {
                unsigned b0 = Bs[(wn * 32 + nt * 8 + grp) * SP + k0 + tig];
                unsigned b1 = Bs[(wn * 32 + nt * 8 + grp) * SP + k0 + tig + 4];
                asm("mma.sync.aligned.m16n8k8.row.col.f32.tf32.tf32.f32 "
                    "{%0,%1,%2,%3},{%4,%5,%6,%7},{%8,%9},{%0,%1,%2,%3};"
                    : "+f"(acc[nt][0]), "+f"(acc[nt][1]), "+f"(acc[nt][2]), "+f"(acc[nt][3])
                    : "r"(a0), "r"(a1), "r"(a2), "r"(a3), "r"(b0), "r"(b1));
            }
        }
        __syncthreads();
    }

    int row0 = mBase + wm * 16 + grp;
#pragma unroll
    for (int nt = 0; nt < 4; nt++) {
        int col = nBase + wn * 32 + nt * 8 + tig * 2;
        C[(size_t)row0 * N + col]           = acc[nt][0];
        C[(size_t)row0 * N + col + 1]       = acc[nt][1];
        C[(size_t)(row0 + 8) * N + col]     = acc[nt][2];
        C[(size_t)(row0 + 8) * N + col + 1] = acc[nt][3];
    }
}

// ---------------- pack conv weights into [768,256] ----------------
__global__ void pack_wall(const float* __restrict__ w1, const float* __restrict__ w2,
                          const float* __restrict__ w3)
{
    int n = blockIdx.x, k4 = threadIdx.x;     // 64 threads x float4 = 256
    const float* src;
    if (n < 128)       src = w1 + n * Dd;
    else if (n < 384) { int m = n - 128; src = w2 + ((m & 127) * 2 + (m >> 7)) * Dd; }
    else              { int m = n - 384; src = w3 + ((m & 127) * 3 + (m >> 7)) * Dd; }
    ((float4*)(g_Wall + n * Dd))[k4] = ((const float4*)src)[k4];
}

// ---------------- segment features: c_w (mean embed), c_h (mean enc) ----------------
__global__ __launch_bounds__(256) void seg_feat(
    const int* __restrict__ word_ids, const float* __restrict__ embed,
    const float* __restrict__ enc)
{
    int r = blockIdx.x;              // b*128 + seg
    int b = r >> 7, seg = r & 127;
    __shared__ int ids[8];
    int tid = threadIdx.x;
    if (tid < 8) ids[tid] = word_ids[b * Ss + seg * Ll + tid];
    __syncthreads();
    {   // c_w: 256 threads == D
        float s = 0.f;
#pragma unroll
        for (int t = 0; t < 8; t++) s += embed[(size_t)ids[t] * Dd + tid];
        g_decin[(size_t)r * DIN + tid] = s * 0.125f;
    }
    for (int k = tid; k < H2; k += 256) {   // c_h
        float s = 0.f;
#pragma unroll
        for (int t = 0; t < 8; t++) s += enc[(size_t)(b * Ss + seg * Ll + t) * H2 + k];
        g_decin[(size_t)r * DIN + Dd + k] = s * 0.125f;
    }
}

// ---------------- conv tap-sum + relu + maxpool ----------------
__global__ __launch_bounds__(128) void conv_reduce(
    const float* __restrict__ b1, const float* __restrict__ b2, const float* __restrict__ b3)
{
    int r = blockIdx.x, f = threadIdx.x;
    const float* U = g_U + (size_t)r * 8 * 768;
    float m1 = -1e30f, m2 = -1e30f, m3 = -1e30f;
#pragma unroll
    for (int t = 0; t < 8; t++) m1 = fmaxf(m1, U[t * 768 + f]);
#pragma unroll
    for (int t = 0; t < 7; t++) m2 = fmaxf(m2, U[t * 768 + 128 + f] + U[(t + 1) * 768 + 256 + f]);
#pragma unroll
    for (int t = 0; t < 6; t++)
        m3 = fmaxf(m3, U[t * 768 + 384 + f] + U[(t + 1) * 768 + 512 + f] + U[(t + 2) * 768 + 640 + f]);
    float* d = g_decin + (size_t)r * DIN + 768;
    d[f]       = fmaxf(m1 + b1[f], 0.f);
    d[128 + f] = fmaxf(m2 + b2[f], 0.f);
    d[256 + f] = fmaxf(m3 + b3[f], 0.f);
}

// ---------------- h0 = [enc fwd last | enc bwd first] ----------------
__global__ void h0_kernel(const float* __restrict__ enc)
{
    int b = blockIdx.x;
    for (int j = threadIdx.x; j < H2; j += blockDim.x) {
        float v = (j < Hh) ? enc[(size_t)(b * Ss + Ss - 1) * H2 + j]
                           : enc[(size_t)(b * Ss) * H2 + j];
        g_h[(size_t)b * H2 + j] = v;
    }
}

// ---------------- persistent LSTM scan (128 CTAs, grid barrier) ----------------
// CTA owns hidden units j0..j0+3 (16 W_hh rows in smem). thread = (b, jj).
__global__ __launch_bounds__(256) void scan_kernel(const float* __restrict__ Whh)
{
    extern __shared__ float sdyn[];
    float* w_s = sdyn;                 // 16 * 516
    float* h_s = sdyn + 16 * 516;      // 64 * 516
    float* c_s = h_s + 64 * 516;       // 256

    int tid = threadIdx.x;
    int j0 = blockIdx.x * 4;
    int b = tid >> 2, jj = tid & 3;

    for (int idx = tid; idx < 16 * 512; idx += 256) {
        int rq = idx >> 9, k = idx & 511;
        int q = rq >> 2, j2 = rq & 3;
        w_s[rq * 516 + k] = Whh[(size_t)(q * H2 + j0 + j2) * H2 + k];
    }
    c_s[tid] = 0.f;
    __syncthreads();

    const float4* w0 = (const float4*)&w_s[(0 + jj) * 516];
    const float4* w1 = (const float4*)&w_s[(4 + jj) * 516];
    const float4* w2 = (const float4*)&w_s[(8 + jj) * 516];
    const float4* w3 = (const float4*)&w_s[(12 + jj) * 516];
    const float4* hp = (const float4*)&h_s[b * 516];

    for (int t = 0; t < NSEG; t++) {
        const float4* src = (const float4*)(g_h + (size_t)t * Bb * H2);
        for (int idx = tid; idx < (Bb * H2) / 4; idx += 256) {
            int bb = idx >> 7, k4 = idx & 127;
            ((float4*)&h_s[bb * 516])[k4] = src[idx];
        }
        __syncthreads();

        size_t gx = (size_t)(b * NSEG + t) * G4 + j0 + jj;
        float a0 = g_gx[gx];
        float a1 = g_gx[gx + 512];
        float a2 = g_gx[gx + 1024];
        float a3 = g_gx[gx + 1536];
#pragma unroll 4
        for (int k4 = 0; k4 < 128; k4++) {
            float4 h4 = hp[k4];
            float4 x0 = w0[k4], x1 = w1[k4], x2 = w2[k4], x3 = w3[k4];
            a0 += h4.x * x0.x + h4.y * x0.y + h4.z * x0.z + h4.w * x0.w;
            a1 += h4.x * x1.x + h4.y * x1.y + h4.z * x1.z + h4.w * x1.w;
            a2 += h4.x * x2.x + h4.y * x2.y + h4.z * x2.z + h4.w * x2.w;
            a3 += h4.x * x3.x + h4.y * x3.y + h4.z * x3.z + h4.w * x3.w;
        }
        float iv = sigmf(a0), fv = sigmf(a1), gv = tanhf(a2), ov = sigmf(a3);
        float c = fv * c_s[tid] + iv * gv;
        c_s[tid] = c;
        g_h[(size_t)(t + 1) * Bb * H2 + b * H2 + j0 + jj] = ov * tanhf(c);

        // grid barrier
        __threadfence();
        __syncthreads();
        if (tid == 0) {
            unsigned gen = g_bar_gen;
            if (atomicAdd(&g_bar_count, 1) == gridDim.x - 1) {
                g_bar_count = 0;
                __threadfence();
                g_bar_gen = gen + 1;
            } else {
                while (g_bar_gen == gen) { }
                __threadfence();
            }
        }
        __syncthreads();
    }
}

// ---------------- log_softmax + output permutation ----------------
__global__ void lsm_kernel(const float* __restrict__ logits, float* __restrict__ out)
{
    int r = blockIdx.x;              // t*64 + b
    int v = threadIdx.x;             // 64 threads
    float x = logits[(size_t)r * Tt + v];
    float m = x;
#pragma unroll
    for (int o = 16; o; o >>= 1) m = fmaxf(m, __shfl_xor_sync(0xffffffffu, m, o));
    __shared__ float s1[2], s2[2];
    if ((v & 31) == 0) s1[v >> 5] = m;
    __syncthreads();
    m = fmaxf(s1[0], s1[1]);
    float s = expf(x - m);
#pragma unroll
    for (int o = 16; o; o >>= 1) s += __shfl_xor_sync(0xffffffffu, s, o);
    if ((v & 31) == 0) s2[v >> 5] = s;
    __syncthreads();
    s = s2[0] + s2[1];
    int t = r >> 6, bb = r & 63;
    out[(size_t)(bb * NSEG + t) * Tt + v] = x - m - logf(s);
}

// ---------------- launcher ----------------
extern "C" void kernel_launch(void* const* d_in, const int* in_sizes, int n_in,
                              void* d_out, int out_size)
{
    const int*   word_ids = (const int*)d_in[0];
    const float* embed    = (const float*)d_in[1];
    const float* enc      = (const float*)d_in[2];
    const float* w1       = (const float*)d_in[3];
    const float* b1       = (const float*)d_in[4];
    const float* w2       = (const float*)d_in[5];
    const float* b2       = (const float*)d_in[6];
    const float* w3       = (const float*)d_in[7];
    const float* b3       = (const float*)d_in[8];
    const float* Wih      = (const float*)d_in[9];
    const float* Whh      = (const float*)d_in[10];
    const float* Wfc      = (const float*)d_in[11];
    float* out = (float*)d_out;

    void *pU, *pWall, *pDecin, *pGx, *pH, *pLog;
    cudaGetSymbolAddress(&pU, g_U);
    cudaGetSymbolAddress(&pWall, g_Wall);
    cudaGetSymbolAddress(&pDecin, g_decin);
    cudaGetSymbolAddress(&pGx, g_gx);
    cudaGetSymbolAddress(&pH, g_h);
    cudaGetSymbolAddress(&pLog, g_logits);

    pack_wall<<<768, 64>>>(w1, w2, w3);
    seg_feat<<<NSEGT, 256>>>(word_ids, embed, enc);

    // conv taps: U[65536,768] = gather(embed)[65536,256] @ Wall^T
    gemm_tf32<<<dim3(768 / BN, NROWS / BM), 256>>>(
        embed, (const float*)pWall, (float*)pU, NROWS, 768, Dd, word_ids);
    conv_reduce<<<NSEGT, 128>>>(b1, b2, b3);

    // gates_x[8192,2048] = dec_in @ W_ih^T
    gemm_tf32<<<dim3(G4 / BN, NSEGT / BM), 256>>>(
        (const float*)pDecin, Wih, (float*)pGx, NSEGT, G4, DIN, nullptr);

    h0_kernel<<<Bb, 256>>>(enc);

    const int scan_smem = (16 * 516 + 64 * 516 + 256) * 4;  // 166144 B
    cudaFuncSetAttribute(scan_kernel, cudaFuncAttributeMaxDynamicSharedMemorySize, scan_smem);
    scan_kernel<<<128, 256, scan_smem>>>(Whh);

    // logits[8192,64] = h(1..128)[8192,512] @ W_fc^T
    gemm_tf32<<<dim3(Tt / BN, NSEGT / BM), 256>>>(
        (const float*)pH + (size_t)Bb * H2, Wfc, (float*)pLog, NSEGT, Tt, H2, nullptr);

    lsm_kernel<<<NSEGT, Tt>>>((const float*)pLog, out);
}

// round 2
// speedup vs baseline: 2.1408x; 2.1408x over previous
#include <cuda_runtime.h>
#include <math.h>

// ---------------- problem constants ----------------
#define Bb    64
#define Ss    1024
#define Dd    256
#define Hh    256
#define H2    512
#define Ff    128
#define Tt    64
#define Ll    8
#define NSEG  128
#define DIN   1152
#define G4    2048           // 4 * H2
#define NROWS 65536          // B * S
#define NSEGT 8192           // B * NSEG

// ---------------- scratch (static device, no allocs) ----------------
__device__ float g_decin[NSEGT * DIN];          // [8192,1152]
__device__ float g_U[(size_t)NROWS * 768];      // conv tap GEMM output
__device__ float g_Wall[768 * Dd];              // stacked conv weights [768,256]
__device__ float g_gx[(size_t)NSEGT * G4];      // gates_x = dec_in @ W_ih^T
__device__ float g_h[(size_t)129 * Bb * H2];    // h per step, slot 0 = h0
__device__ float g_logits[(size_t)NSEGT * Tt];
__device__ unsigned g_bar_count;
__device__ volatile unsigned g_bar_gen;

// ---------------- helpers ----------------
__device__ __forceinline__ unsigned f2tf(float x) {
    unsigned u;
    asm("cvt.rna.tf32.f32 %0, %1;" : "=r"(u) : "f"(x));
    return u;
}
__device__ __forceinline__ float sigmf(float x) { return 1.f / (1.f + __expf(-x)); }

#define MMA_TF32(acc, a0, a1, a2, a3, b0, b1)                                  \
    asm("mma.sync.aligned.m16n8k8.row.col.f32.tf32.tf32.f32 "                  \
        "{%0,%1,%2,%3},{%4,%5,%6,%7},{%8,%9},{%0,%1,%2,%3};"                   \
        : "+f"(acc[0]), "+f"(acc[1]), "+f"(acc[2]), "+f"(acc[3])               \
        : "r"(a0), "r"(a1), "r"(a2), "r"(a3), "r"(b0), "r"(b1))

#define CP_ASYNC16(dst, src)                                                   \
    asm volatile("cp.async.cg.shared.global [%0], [%1], 16;\n" ::              \
                 "r"(dst), "l"(src))

// ================= double-buffered tf32 GEMM =================
// C[M,N] = A[M,K] @ B[N,K]^T ; gather: A row m -> A[gather[m]]
#define GBM 128
#define GBN 64
#define GBK 32
#define GSP 36
#define GEMM2_SMEM ((2 * GBM * GSP + 2 * GBN * GSP) * 4)   // 55296 B

__global__ __launch_bounds__(256) void gemm2(
    const float* __restrict__ A, const float* __restrict__ Bw,
    float* __restrict__ C, int M, int N, int K,
    const int* __restrict__ gather)
{
    extern __shared__ unsigned gsm[];
    unsigned* AsAll = gsm;                         // 2 * 4608
    unsigned* BsAll = gsm + 2 * GBM * GSP;         // 2 * 2304
    __shared__ int rows_s[GBM];

    int tid = threadIdx.x;
    int mBase = blockIdx.y * GBM, nBase = blockIdx.x * GBN;
    if (tid < GBM) rows_s[tid] = gather ? gather[mBase + tid] : (mBase + tid);
    __syncthreads();

    int w = tid >> 5, lane = tid & 31;
    int grp = lane >> 2, tig = lane & 3;
    int wm = w & 3, wn = w >> 2;    // warp grid 4x2, warp tile 32x32

    float acc[2][4][4];
#pragma unroll
    for (int mt = 0; mt < 2; mt++)
#pragma unroll
        for (int nt = 0; nt < 4; nt++)
#pragma unroll
            for (int i = 0; i < 4; i++) acc[mt][nt][i] = 0.f;

    int nkt = K / GBK;

    // stage loader
#define GLOAD(s, kt) do {                                                       \
        int koff = (kt) * GBK;                                                  \
        _Pragma("unroll")                                                       \
        for (int i = 0; i < 4; i++) {                                           \
            int cid = tid + i * 256;                                            \
            int row = cid >> 3, ch = (cid & 7) * 4;                             \
            const float* src = A + (size_t)rows_s[row] * K + koff + ch;         \
            unsigned dst = (unsigned)__cvta_generic_to_shared(                  \
                &AsAll[(s) * GBM * GSP + row * GSP + ch]);                      \
            CP_ASYNC16(dst, src);                                               \
        }                                                                       \
        _Pragma("unroll")                                                       \
        for (int i = 0; i < 2; i++) {                                           \
            int cid = tid + i * 256;                                            \
            int row = cid >> 3, ch = (cid & 7) * 4;                             \
            const float* src = Bw + (size_t)(nBase + row) * K + koff + ch;      \
            unsigned dst = (unsigned)__cvta_generic_to_shared(                  \
                &BsAll[(s) * GBN * GSP + row * GSP + ch]);                      \
            CP_ASYNC16(dst, src);                                               \
        }                                                                       \
        asm volatile("cp.async.commit_group;\n");                               \
    } while (0)

    GLOAD(0, 0);

    for (int kt = 0; kt < nkt; kt++) {
        int s = kt & 1;
        if (kt + 1 < nkt) {
            GLOAD((kt + 1) & 1, kt + 1);
            asm volatile("cp.async.wait_group 1;\n" ::: "memory");
        } else {
            asm volatile("cp.async.wait_group 0;\n" ::: "memory");
        }
        __syncthreads();

        const unsigned* As = AsAll + s * GBM * GSP;
        const unsigned* Bs = BsAll + s * GBN * GSP;
#pragma unroll
        for (int ks = 0; ks < 4; ks++) {
            int k0 = ks * 8;
            unsigned a[2][4];
#pragma unroll
            for (int mt = 0; mt < 2; mt++) {
                int r = wm * 32 + mt * 16;
                a[mt][0] = f2tf(__uint_as_float(As[(r + grp) * GSP + k0 + tig]));
                a[mt][1] = f2tf(__uint_as_float(As[(r + grp + 8) * GSP + k0 + tig]));
                a[mt][2] = f2tf(__uint_as_float(As[(r + grp) * GSP + k0 + tig + 4]));
                a[mt][3] = f2tf(__uint_as_float(As[(r + grp + 8) * GSP + k0 + tig + 4]));
            }
#pragma unroll
            for (int nt = 0; nt < 4; nt++) {
                unsigned b0 = f2tf(__uint_as_float(Bs[(wn * 32 + nt * 8 + grp) * GSP + k0 + tig]));
                unsigned b1 = f2tf(__uint_as_float(Bs[(wn * 32 + nt * 8 + grp) * GSP + k0 + tig + 4]));
#pragma unroll
                for (int mt = 0; mt < 2; mt++)
                    MMA_TF32(acc[mt][nt], a[mt][0], a[mt][1], a[mt][2], a[mt][3], b0, b1);
            }
        }
        __syncthreads();
    }

#pragma unroll
    for (int mt = 0; mt < 2; mt++) {
        int row0 = mBase + wm * 32 + mt * 16 + grp;
#pragma unroll
        for (int nt = 0; nt < 4; nt++) {
            int col = nBase + wn * 32 + nt * 8 + tig * 2;
            float2 v0 = make_float2(acc[mt][nt][0], acc[mt][nt][1]);
            float2 v1 = make_float2(acc[mt][nt][2], acc[mt][nt][3]);
            *(float2*)&C[(size_t)row0 * N + col] = v0;
            *(float2*)&C[(size_t)(row0 + 8) * N + col] = v1;
        }
    }
}

// ---------------- pack conv weights into [768,256] ----------------
__global__ void pack_wall(const float* __restrict__ w1, const float* __restrict__ w2,
                          const float* __restrict__ w3)
{
    int n = blockIdx.x, k4 = threadIdx.x;
    const float* src;
    if (n < 128)       src = w1 + n * Dd;
    else if (n < 384) { int m = n - 128; src = w2 + ((m & 127) * 2 + (m >> 7)) * Dd; }
    else              { int m = n - 384; src = w3 + ((m & 127) * 3 + (m >> 7)) * Dd; }
    ((float4*)(g_Wall + n * Dd))[k4] = ((const float4*)src)[k4];
}

// ---------------- segment features ----------------
__global__ __launch_bounds__(256) void seg_feat(
    const int* __restrict__ word_ids, const float* __restrict__ embed,
    const float* __restrict__ enc)
{
    int r = blockIdx.x;
    int b = r >> 7, seg = r & 127;
    __shared__ int ids[8];
    int tid = threadIdx.x;
    if (tid < 8) ids[tid] = word_ids[b * Ss + seg * Ll + tid];
    __syncthreads();
    {
        float s = 0.f;
#pragma unroll
        for (int t = 0; t < 8; t++) s += embed[(size_t)ids[t] * Dd + tid];
        g_decin[(size_t)r * DIN + tid] = s * 0.125f;
    }
    for (int k = tid; k < H2; k += 256) {
        float s = 0.f;
#pragma unroll
        for (int t = 0; t < 8; t++) s += enc[(size_t)(b * Ss + seg * Ll + t) * H2 + k];
        g_decin[(size_t)r * DIN + Dd + k] = s * 0.125f;
    }
}

// ---------------- conv tap-sum + relu + maxpool ----------------
__global__ __launch_bounds__(128) void conv_reduce(
    const float* __restrict__ b1, const float* __restrict__ b2, const float* __restrict__ b3)
{
    int r = blockIdx.x, f = threadIdx.x;
    const float* U = g_U + (size_t)r * 8 * 768;
    float m1 = -1e30f, m2 = -1e30f, m3 = -1e30f;
#pragma unroll
    for (int t = 0; t < 8; t++) m1 = fmaxf(m1, U[t * 768 + f]);
#pragma unroll
    for (int t = 0; t < 7; t++) m2 = fmaxf(m2, U[t * 768 + 128 + f] + U[(t + 1) * 768 + 256 + f]);
#pragma unroll
    for (int t = 0; t < 6; t++)
        m3 = fmaxf(m3, U[t * 768 + 384 + f] + U[(t + 1) * 768 + 512 + f] + U[(t + 2) * 768 + 640 + f]);
    float* d = g_decin + (size_t)r * DIN + 768;
    d[f]       = fmaxf(m1 + b1[f], 0.f);
    d[128 + f] = fmaxf(m2 + b2[f], 0.f);
    d[256 + f] = fmaxf(m3 + b3[f], 0.f);
}

// ---------------- h0 ----------------
__global__ void h0_kernel(const float* __restrict__ enc)
{
    int b = blockIdx.x;
    for (int j = threadIdx.x; j < H2; j += blockDim.x) {
        float v = (j < Hh) ? enc[(size_t)(b * Ss + Ss - 1) * H2 + j]
                           : enc[(size_t)(b * Ss) * H2 + j];
        g_h[(size_t)b * H2 + j] = v;
    }
}

// ================= tensor-core LSTM scan =================
// 128 CTAs x 512 threads. CTA owns hidden units j0..j0+3 (16 gate cols,
// col c = q*4+jj). W_hh fragments live in REGISTERS for the whole scan.
// Warp w: mt = w&3 (16 batch rows), kq = w>>2 (K quarter of 128).
// h broadcast via gmem; per-step smem A read = exactly 128KB (ldmatrix).
#define SC_P 516
#define SCAN_SMEM (64 * SC_P * 4 + 4 * 64 * 18 * 4)   // 132096 + 18432

__global__ __launch_bounds__(512, 1) void scan2(const float* __restrict__ Whh)
{
    extern __shared__ unsigned ssm[];
    unsigned* hA  = ssm;                          // [64][516] tf32
    float*    pbuf = (float*)(ssm + 64 * SC_P);   // [4][64][18] K-partials

    int tid = threadIdx.x;
    int lane = tid & 31, w = tid >> 5;
    int grp = lane >> 2, tig = lane & 3;
    int mt = w & 3, kq = w >> 2;
    int j0 = blockIdx.x * 4;

    // W fragments -> registers (loop-invariant B operand)
    unsigned blo[2][16], bhi[2][16];
#pragma unroll
    for (int nt = 0; nt < 2; nt++) {
        int c = nt * 8 + grp;                    // gate col: q = c>>2, jj = c&3
        const float* wr = Whh + (size_t)((c >> 2) * H2 + j0 + (c & 3)) * H2 + kq * 128;
#pragma unroll
        for (int ki = 0; ki < 16; ki++) {
            blo[nt][ki] = f2tf(wr[ki * 8 + tig]);
            bhi[nt][ki] = f2tf(wr[ki * 8 + tig + 4]);
        }
    }

    float c_st = 0.f;   // cell state (threads < 256: item (b, jj))
    unsigned hA_u32 = (unsigned)__cvta_generic_to_shared(hA);
    unsigned ldbase = hA_u32
        + (unsigned)((mt * 16 + (lane & 15)) * (SC_P * 4) + ((lane >> 4) << 4) + kq * 512);

    for (int t = 0; t < NSEG; t++) {
        // stage h_t (fp32 gmem -> tf32 smem), 128KB
        const float4* src = (const float4*)(g_h + (size_t)t * Bb * H2);
#pragma unroll
        for (int i = 0; i < 16; i++) {
            int idx = tid + i * 512;
            int bb = idx >> 7, k4 = idx & 127;
            float4 v = src[idx];
            unsigned* d = &hA[bb * SC_P + k4 * 4];
            d[0] = f2tf(v.x); d[1] = f2tf(v.y); d[2] = f2tf(v.z); d[3] = f2tf(v.w);
        }
        __syncthreads();

        // gates[64x16] partial over this warp's K quarter
        float acc0[4] = {0, 0, 0, 0}, acc1[4] = {0, 0, 0, 0};
#pragma unroll
        for (int ki = 0; ki < 16; ki++) {
            unsigned a0, a1, a2, a3;
            unsigned addr = ldbase + ki * 32;
            asm volatile("ldmatrix.sync.aligned.m8n8.x4.shared.b16 {%0,%1,%2,%3}, [%4];"
                         : "=r"(a0), "=r"(a1), "=r"(a2), "=r"(a3) : "r"(addr));
            MMA_TF32(acc0, a0, a1, a2, a3, blo[0][ki], bhi[0][ki]);
            MMA_TF32(acc1, a0, a1, a2, a3, blo[1][ki], bhi[1][ki]);
        }
        {
            float* pb = pbuf + kq * (64 * 18);
            int row = mt * 16 + grp, c0 = tig * 2;
            pb[row * 18 + c0]           = acc0[0];
            pb[row * 18 + c0 + 1]       = acc0[1];
            pb[(row + 8) * 18 + c0]     = acc0[2];
            pb[(row + 8) * 18 + c0 + 1] = acc0[3];
            pb[row * 18 + 8 + c0]           = acc1[0];
            pb[row * 18 + 8 + c0 + 1]       = acc1[1];
            pb[(row + 8) * 18 + 8 + c0]     = acc1[2];
            pb[(row + 8) * 18 + 8 + c0 + 1] = acc1[3];
        }
        __syncthreads();

        if (tid < 256) {
            int b = tid >> 2, jj = tid & 3;
            size_t gxo = (size_t)(b * NSEG + t) * G4 + j0 + jj;
            float gsum[4];
#pragma unroll
            for (int q = 0; q < 4; q++) {
                int col = q * 4 + jj;
                gsum[q] = pbuf[b * 18 + col] + pbuf[1152 + b * 18 + col]
                        + pbuf[2304 + b * 18 + col] + pbuf[3456 + b * 18 + col];
            }
            float gi = gsum[0] + g_gx[gxo];
            float gf = gsum[1] + g_gx[gxo + 512];
            float gg = gsum[2] + g_gx[gxo + 1024];
            float go = gsum[3] + g_gx[gxo + 1536];
            c_st = sigmf(gf) * c_st + sigmf(gi) * tanhf(gg);
            g_h[(size_t)(t + 1) * Bb * H2 + (size_t)b * H2 + j0 + jj] = sigmf(go) * tanhf(c_st);
        }

        // grid barrier
        __threadfence();
        __syncthreads();
        if (tid == 0) {
            unsigned gen = g_bar_gen;
            if (atomicAdd(&g_bar_count, 1) == gridDim.x - 1) {
                g_bar_count = 0;
                __threadfence();
                g_bar_gen = gen + 1;
            } else {
                while (g_bar_gen == gen) { }
                __threadfence();
            }
        }
        __syncthreads();
    }
}

// ---------------- log_softmax + output permutation ----------------
__global__ void lsm_kernel(const float* __restrict__ logits, float* __restrict__ out)
{
    int r = blockIdx.x;              // t*64 + b
    int v = threadIdx.x;             // 64 threads
    float x = logits[(size_t)r * Tt + v];
    float m = x;
#pragma unroll
    for (int o = 16; o; o >>= 1) m = fmaxf(m, __shfl_xor_sync(0xffffffffu, m, o));
    __shared__ float s1[2], s2[2];
    if ((v & 31) == 0) s1[v >> 5] = m;
    __syncthreads();
    m = fmaxf(s1[0], s1[1]);
    float s = expf(x - m);
#pragma unroll
    for (int o = 16; o; o >>= 1) s += __shfl_xor_sync(0xffffffffu, s, o);
    if ((v & 31) == 0) s2[v >> 5] = s;
    __syncthreads();
    s = s2[0] + s2[1];
    int t = r >> 6, bb = r & 63;
    out[(size_t)(bb * NSEG + t) * Tt + v] = x - m - logf(s);
}

// ---------------- launcher ----------------
extern "C" void kernel_launch(void* const* d_in, const int* in_sizes, int n_in,
                              void* d_out, int out_size)
{
    const int*   word_ids = (const int*)d_in[0];
    const float* embed    = (const float*)d_in[1];
    const float* enc      = (const float*)d_in[2];
    const float* w1       = (const float*)d_in[3];
    const float* b1       = (const float*)d_in[4];
    const float* w2       = (const float*)d_in[5];
    const float* b2       = (const float*)d_in[6];
    const float* w3       = (const float*)d_in[7];
    const float* b3       = (const float*)d_in[8];
    const float* Wih      = (const float*)d_in[9];
    const float* Whh      = (const float*)d_in[10];
    const float* Wfc      = (const float*)d_in[11];
    float* out = (float*)d_out;

    void *pU, *pWall, *pDecin, *pGx, *pH, *pLog;
    cudaGetSymbolAddress(&pU, g_U);
    cudaGetSymbolAddress(&pWall, g_Wall);
    cudaGetSymbolAddress(&pDecin, g_decin);
    cudaGetSymbolAddress(&pGx, g_gx);
    cudaGetSymbolAddress(&pH, g_h);
    cudaGetSymbolAddress(&pLog, g_logits);

    cudaFuncSetAttribute(gemm2, cudaFuncAttributeMaxDynamicSharedMemorySize, GEMM2_SMEM);
    cudaFuncSetAttribute(scan2, cudaFuncAttributeMaxDynamicSharedMemorySize, SCAN_SMEM);

    pack_wall<<<768, 64>>>(w1, w2, w3);
    seg_feat<<<NSEGT, 256>>>(word_ids, embed, enc);

    // conv taps: U[65536,768] = gather(embed) @ Wall^T
    gemm2<<<dim3(768 / GBN, NROWS / GBM), 256, GEMM2_SMEM>>>(
        embed, (const float*)pWall, (float*)pU, NROWS, 768, Dd, word_ids);
    conv_reduce<<<NSEGT, 128>>>(b1, b2, b3);

    // gates_x[8192,2048] = dec_in @ W_ih^T
    gemm2<<<dim3(G4 / GBN, NSEGT / GBM), 256, GEMM2_SMEM>>>(
        (const float*)pDecin, Wih, (float*)pGx, NSEGT, G4, DIN, nullptr);

    h0_kernel<<<Bb, 256>>>(enc);

    scan2<<<128, 512, SCAN_SMEM>>>(Whh);

    // logits[8192,64] = h(1..128) @ W_fc^T
    gemm2<<<dim3(Tt / GBN, NSEGT / GBM), 256, GEMM2_SMEM>>>(
        (const float*)pH + (size_t)Bb * H2, Wfc, (float*)pLog, NSEGT, Tt, H2, nullptr);

    lsm_kernel<<<NSEGT, Tt>>>((const float*)pLog, out);
}

// round 3
// speedup vs baseline: 2.4541x; 1.1463x over previous
#include <cuda_runtime.h>
#include <math.h>

// ---------------- problem constants ----------------
#define Bb    64
#define Ss    1024
#define Dd    256
#define Hh    256
#define H2    512
#define Ff    128
#define Tt    64
#define Ll    8
#define NSEG  128
#define DIN   1152
#define G4    2048           // 4 * H2
#define NROWS 65536          // B * S
#define NSEGT 8192           // B * NSEG

// ---------------- scratch (static device, no allocs) ----------------
__device__ float g_decin[NSEGT * DIN];          // [8192,1152]
__device__ float g_U[(size_t)NROWS * 768];      // conv tap GEMM output
__device__ float g_Wall[768 * Dd];              // stacked conv weights [768,256]
__device__ float g_gx[(size_t)NSEGT * G4];      // gates_x = dec_in @ W_ih^T
__device__ float g_h[(size_t)129 * Bb * H2];    // h per step (tf32 bits), slot 0 = h0
__device__ float g_logits[(size_t)NSEGT * Tt];
__device__ unsigned g_bar_count;

// ---------------- helpers ----------------
__device__ __forceinline__ unsigned f2tf(float x) {
    unsigned u;
    asm("cvt.rna.tf32.f32 %0, %1;" : "=r"(u) : "f"(x));
    return u;
}
__device__ __forceinline__ float sigmf(float x) { return 1.f / (1.f + __expf(-x)); }
__device__ __forceinline__ float tanhfast(float x) { return 2.f / (1.f + __expf(-2.f * x)) - 1.f; }

#define MMA_TF32(acc, a0, a1, a2, a3, b0, b1)                                  \
    asm("mma.sync.aligned.m16n8k8.row.col.f32.tf32.tf32.f32 "                  \
        "{%0,%1,%2,%3},{%4,%5,%6,%7},{%8,%9},{%0,%1,%2,%3};"                   \
        : "+f"(acc[0]), "+f"(acc[1]), "+f"(acc[2]), "+f"(acc[3])               \
        : "r"(a0), "r"(a1), "r"(a2), "r"(a3), "r"(b0), "r"(b1))

#define CP_ASYNC16(dst, src)                                                   \
    asm volatile("cp.async.cg.shared.global [%0], [%1], 16;\n" ::              \
                 "r"(dst), "l"(src))

// ================= 128x128 double-buffered tf32 GEMM =================
// C[M,N] = A[M,K] @ B[N,K]^T ; gather: A row m -> A[gather[m]]
#define HBM 128
#define HBN 128
#define HBK 32
#define HSP 36
#define GEMM3_SMEM ((2 * HBM * HSP + 2 * HBN * HSP) * 4)   // 73728 B

__global__ __launch_bounds__(256) void gemm3(
    const float* __restrict__ A, const float* __restrict__ Bw,
    float* __restrict__ C, int M, int N, int K,
    const int* __restrict__ gather)
{
    extern __shared__ unsigned gsm[];
    unsigned* AsAll = gsm;                         // 2 * 4608
    unsigned* BsAll = gsm + 2 * HBM * HSP;
    __shared__ int rows_s[HBM];

    int tid = threadIdx.x;
    int mBase = blockIdx.y * HBM, nBase = blockIdx.x * HBN;
    if (tid < HBM) rows_s[tid] = gather ? gather[mBase + tid] : (mBase + tid);
    __syncthreads();

    int w = tid >> 5, lane = tid & 31;
    int grp = lane >> 2, tig = lane & 3;
    int wm = w & 1, wn = w >> 1;    // 2x4 warp grid, warp tile 64x32

    float acc[4][4][4];
#pragma unroll
    for (int mt = 0; mt < 4; mt++)
#pragma unroll
        for (int nt = 0; nt < 4; nt++)
#pragma unroll
            for (int i = 0; i < 4; i++) acc[mt][nt][i] = 0.f;

    int nkt = K / HBK;

#define GLOAD3(s, kt) do {                                                      \
        int koff = (kt) * HBK;                                                  \
        _Pragma("unroll")                                                       \
        for (int i = 0; i < 4; i++) {                                           \
            int cid = tid + i * 256;                                            \
            int row = cid >> 3, ch = (cid & 7) * 4;                             \
            const float* src = A + (size_t)rows_s[row] * K + koff + ch;         \
            unsigned dst = (unsigned)__cvta_generic_to_shared(                  \
                &AsAll[(s) * HBM * HSP + row * HSP + ch]);                      \
            CP_ASYNC16(dst, src);                                               \
        }                                                                       \
        _Pragma("unroll")                                                       \
        for (int i = 0; i < 4; i++) {                                           \
            int cid = tid + i * 256;                                            \
            int row = cid >> 3, ch = (cid & 7) * 4;                             \
            const float* src = Bw + (size_t)(nBase + row) * K + koff + ch;      \
            unsigned dst = (unsigned)__cvta_generic_to_shared(                  \
                &BsAll[(s) * HBN * HSP + row * HSP + ch]);                      \
            CP_ASYNC16(dst, src);                                               \
        }                                                                       \
        asm volatile("cp.async.commit_group;\n");                               \
    } while (0)

    GLOAD3(0, 0);

    for (int kt = 0; kt < nkt; kt++) {
        int s = kt & 1;
        if (kt + 1 < nkt) {
            GLOAD3((kt + 1) & 1, kt + 1);
            asm volatile("cp.async.wait_group 1;\n" ::: "memory");
        } else {
            asm volatile("cp.async.wait_group 0;\n" ::: "memory");
        }
        __syncthreads();

        const unsigned* As = AsAll + s * HBM * HSP;
        const unsigned* Bs = BsAll + s * HBN * HSP;
#pragma unroll
        for (int ks = 0; ks < 4; ks++) {
            int k0 = ks * 8;
            unsigned a[4][4];
#pragma unroll
            for (int mt = 0; mt < 4; mt++) {
                int r = wm * 64 + mt * 16;
                a[mt][0] = f2tf(__uint_as_float(As[(r + grp) * HSP + k0 + tig]));
                a[mt][1] = f2tf(__uint_as_float(As[(r + grp + 8) * HSP + k0 + tig]));
                a[mt][2] = f2tf(__uint_as_float(As[(r + grp) * HSP + k0 + tig + 4]));
                a[mt][3] = f2tf(__uint_as_float(As[(r + grp + 8) * HSP + k0 + tig + 4]));
            }
#pragma unroll
            for (int nt = 0; nt < 4; nt++) {
                unsigned b0 = f2tf(__uint_as_float(Bs[(wn * 32 + nt * 8 + grp) * HSP + k0 + tig]));
                unsigned b1 = f2tf(__uint_as_float(Bs[(wn * 32 + nt * 8 + grp) * HSP + k0 + tig + 4]));
#pragma unroll
                for (int mt = 0; mt < 4; mt++)
                    MMA_TF32(acc[mt][nt], a[mt][0], a[mt][1], a[mt][2], a[mt][3], b0, b1);
            }
        }
        __syncthreads();
    }

#pragma unroll
    for (int mt = 0; mt < 4; mt++) {
        int row0 = mBase + wm * 64 + mt * 16 + grp;
#pragma unroll
        for (int nt = 0; nt < 4; nt++) {
            int col = nBase + wn * 32 + nt * 8 + tig * 2;
            *(float2*)&C[(size_t)row0 * N + col] = make_float2(acc[mt][nt][0], acc[mt][nt][1]);
            *(float2*)&C[(size_t)(row0 + 8) * N + col] = make_float2(acc[mt][nt][2], acc[mt][nt][3]);
        }
    }
}

// ================= 128x64 GEMM for the small logits GEMM =================
#define GBM 128
#define GBN 64
#define GSP 36
#define GEMM2_SMEM ((2 * GBM * GSP + 2 * GBN * GSP) * 4)   // 55296 B

__global__ __launch_bounds__(256) void gemm2(
    const float* __restrict__ A, const float* __restrict__ Bw,
    float* __restrict__ C, int M, int N, int K)
{
    extern __shared__ unsigned gsm[];
    unsigned* AsAll = gsm;
    unsigned* BsAll = gsm + 2 * GBM * GSP;

    int tid = threadIdx.x;
    int mBase = blockIdx.y * GBM, nBase = blockIdx.x * GBN;

    int w = tid >> 5, lane = tid & 31;
    int grp = lane >> 2, tig = lane & 3;
    int wm = w & 3, wn = w >> 2;    // 4x2, warp tile 32x32

    float acc[2][4][4];
#pragma unroll
    for (int mt = 0; mt < 2; mt++)
#pragma unroll
        for (int nt = 0; nt < 4; nt++)
#pragma unroll
            for (int i = 0; i < 4; i++) acc[mt][nt][i] = 0.f;

    int nkt = K / HBK;

#define GLOAD2(s, kt) do {                                                      \
        int koff = (kt) * HBK;                                                  \
        _Pragma("unroll")                                                       \
        for (int i = 0; i < 4; i++) {                                           \
            int cid = tid + i * 256;                                            \
            int row = cid >> 3, ch = (cid & 7) * 4;                             \
            const float* src = A + (size_t)(mBase + row) * K + koff + ch;       \
            unsigned dst = (unsigned)__cvta_generic_to_shared(                  \
                &AsAll[(s) * GBM * GSP + row * GSP + ch]);                      \
            CP_ASYNC16(dst, src);                                               \
        }                                                                       \
        _Pragma("unroll")                                                       \
        for (int i = 0; i < 2; i++) {                                           \
            int cid = tid + i * 256;                                            \
            int row = cid >> 3, ch = (cid & 7) * 4;                             \
            const float* src = Bw + (size_t)(nBase + row) * K + koff + ch;      \
            unsigned dst = (unsigned)__cvta_generic_to_shared(                  \
                &BsAll[(s) * GBN * GSP + row * GSP + ch]);                      \
            CP_ASYNC16(dst, src);                                               \
        }                                                                       \
        asm volatile("cp.async.commit_group;\n");                               \
    } while (0)

    GLOAD2(0, 0);

    for (int kt = 0; kt < nkt; kt++) {
        int s = kt & 1;
        if (kt + 1 < nkt) {
            GLOAD2((kt + 1) & 1, kt + 1);
            asm volatile("cp.async.wait_group 1;\n" ::: "memory");
        } else {
            asm volatile("cp.async.wait_group 0;\n" ::: "memory");
        }
        __syncthreads();

        const unsigned* As = AsAll + s * GBM * GSP;
        const unsigned* Bs = BsAll + s * GBN * GSP;
#pragma unroll
        for (int ks = 0; ks < 4; ks++) {
            int k0 = ks * 8;
            unsigned a[2][4];
#pragma unroll
            for (int mt = 0; mt < 2; mt++) {
                int r = wm * 32 + mt * 16;
                a[mt][0] = f2tf(__uint_as_float(As[(r + grp) * GSP + k0 + tig]));
                a[mt][1] = f2tf(__uint_as_float(As[(r + grp + 8) * GSP + k0 + tig]));
                a[mt][2] = f2tf(__uint_as_float(As[(r + grp) * GSP + k0 + tig + 4]));
                a[mt][3] = f2tf(__uint_as_float(As[(r + grp + 8) * GSP + k0 + tig + 4]));
            }
#pragma unroll
            for (int nt = 0; nt < 4; nt++) {
                unsigned b0 = f2tf(__uint_as_float(Bs[(wn * 32 + nt * 8 + grp) * GSP + k0 + tig]));
                unsigned b1 = f2tf(__uint_as_float(Bs[(wn * 32 + nt * 8 + grp) * GSP + k0 + tig + 4]));
#pragma unroll
                for (int mt = 0; mt < 2; mt++)
                    MMA_TF32(acc[mt][nt], a[mt][0], a[mt][1], a[mt][2], a[mt][3], b0, b1);
            }
        }
        __syncthreads();
    }

#pragma unroll
    for (int mt = 0; mt < 2; mt++) {
        int row0 = mBase + wm * 32 + mt * 16 + grp;
#pragma unroll
        for (int nt = 0; nt < 4; nt++) {
            int col = nBase + wn * 32 + nt * 8 + tig * 2;
            *(float2*)&C[(size_t)row0 * N + col] = make_float2(acc[mt][nt][0], acc[mt][nt][1]);
            *(float2*)&C[(size_t)(row0 + 8) * N + col] = make_float2(acc[mt][nt][2], acc[mt][nt][3]);
        }
    }
}

// ---------------- pack conv weights into [768,256] ----------------
__global__ void pack_wall(const float* __restrict__ w1, const float* __restrict__ w2,
                          const float* __restrict__ w3)
{
    int n = blockIdx.x, k4 = threadIdx.x;
    const float* src;
    if (n < 128)       src = w1 + n * Dd;
    else if (n < 384) { int m = n - 128; src = w2 + ((m & 127) * 2 + (m >> 7)) * Dd; }
    else              { int m = n - 384; src = w3 + ((m & 127) * 3 + (m >> 7)) * Dd; }
    ((float4*)(g_Wall + n * Dd))[k4] = ((const float4*)src)[k4];
}

// ---------------- segment features ----------------
__global__ __launch_bounds__(256) void seg_feat(
    const int* __restrict__ word_ids, const float* __restrict__ embed,
    const float* __restrict__ enc)
{
    int r = blockIdx.x;
    int b = r >> 7, seg = r & 127;
    __shared__ int ids[8];
    int tid = threadIdx.x;
    if (tid < 8) ids[tid] = word_ids[b * Ss + seg * Ll + tid];
    __syncthreads();
    {
        float s = 0.f;
#pragma unroll
        for (int t = 0; t < 8; t++) s += embed[(size_t)ids[t] * Dd + tid];
        g_decin[(size_t)r * DIN + tid] = s * 0.125f;
    }
    for (int k = tid; k < H2; k += 256) {
        float s = 0.f;
#pragma unroll
        for (int t = 0; t < 8; t++) s += enc[(size_t)(b * Ss + seg * Ll + t) * H2 + k];
        g_decin[(size_t)r * DIN + Dd + k] = s * 0.125f;
    }
}

// ---------------- conv tap-sum + relu + maxpool ----------------
__global__ __launch_bounds__(128) void conv_reduce(
    const float* __restrict__ b1, const float* __restrict__ b2, const float* __restrict__ b3)
{
    int r = blockIdx.x, f = threadIdx.x;
    const float* U = g_U + (size_t)r * 8 * 768;
    float m1 = -1e30f, m2 = -1e30f, m3 = -1e30f;
#pragma unroll
    for (int t = 0; t < 8; t++) m1 = fmaxf(m1, U[t * 768 + f]);
#pragma unroll
    for (int t = 0; t < 7; t++) m2 = fmaxf(m2, U[t * 768 + 128 + f] + U[(t + 1) * 768 + 256 + f]);
#pragma unroll
    for (int t = 0; t < 6; t++)
        m3 = fmaxf(m3, U[t * 768 + 384 + f] + U[(t + 1) * 768 + 512 + f] + U[(t + 2) * 768 + 640 + f]);
    float* d = g_decin + (size_t)r * DIN + 768;
    d[f]       = fmaxf(m1 + b1[f], 0.f);
    d[128 + f] = fmaxf(m2 + b2[f], 0.f);
    d[256 + f] = fmaxf(m3 + b3[f], 0.f);
}

// ---------------- h0 (stored as tf32 bits) + barrier reset ----------------
__global__ void h0_kernel(const float* __restrict__ enc)
{
    if (blockIdx.x == 0 && threadIdx.x == 0) g_bar_count = 0;
    int b = blockIdx.x;
    for (int j = threadIdx.x; j < H2; j += blockDim.x) {
        float v = (j < Hh) ? enc[(size_t)(b * Ss + Ss - 1) * H2 + j]
                           : enc[(size_t)(b * Ss) * H2 + j];
        g_h[(size_t)b * H2 + j] = __uint_as_float(f2tf(v));
    }
}

// ================= tensor-core LSTM scan, 2-D split =================
// 128 CTAs = 64 col-groups (8 hidden units = 32 gate cols) x 2 batch-groups
// (32 rows). W_hh fragments in registers for the whole scan. h stored as tf32
// bits in gmem; staged via cp.async (64KB/CTA/step -> 8MB/step chip-wide).
#define SC_P 516
#define SCAN3_SMEM ((32 * SC_P + 8 * 32 * 34) * 4)   // 100864 B

__global__ __launch_bounds__(512, 1) void scan3(const float* __restrict__ Whh)
{
    extern __shared__ unsigned ssm[];
    unsigned* hA = ssm;                       // [32][516] tf32 bits
    float* pbuf = (float*)(ssm + 32 * SC_P);  // [8 kq][32 rows][34]

    int tid = threadIdx.x;
    int lane = tid & 31, w = tid >> 5;
    int grp = lane >> 2, tig = lane & 3;
    int mt = w & 1;          // 16-row tile within 32
    int kq = w >> 1;         // 0..7, 64-wide K slice
    int cid = blockIdx.x;
    int bg = cid & 1;        // batch rows bg*32..+31
    int j0 = (cid >> 1) * 8; // 8 hidden units

    // W_hh fragments -> registers. n-tile nt == gate q; jj == grp.
    unsigned blo[4][8], bhi[4][8];
#pragma unroll
    for (int nt = 0; nt < 4; nt++) {
        const float* wr = Whh + (size_t)(nt * H2 + j0 + grp) * H2 + kq * 64;
#pragma unroll
        for (int ki = 0; ki < 8; ki++) {
            blo[nt][ki] = f2tf(wr[ki * 8 + tig]);
            bhi[nt][ki] = f2tf(wr[ki * 8 + tig + 4]);
        }
    }

    const unsigned* ghu = (const unsigned*)g_h;
    unsigned* ghw = (unsigned*)g_h;
    unsigned* pcount = &g_bar_count;

    float c_st = 0.f;        // threads < 256: (b_hat = tid>>3, jj = tid&7)
    int b_hat = tid >> 3, jj = tid & 7;
    int row_global = bg * 32 + b_hat;

    unsigned hA_u32 = (unsigned)__cvta_generic_to_shared(hA);
    unsigned ldbase = hA_u32
        + (unsigned)((mt * 16 + (lane & 15)) * (SC_P * 4) + ((lane >> 4) << 4) + kq * 256);

    for (int t = 0; t < NSEG; t++) {
        // stage h_t slice (32 rows x 512 u32) via cp.async — no RF traffic
        {
            const unsigned* src = ghu + (size_t)t * Bb * H2 + (size_t)bg * 32 * H2;
#pragma unroll
            for (int i = 0; i < 8; i++) {
                int idx = tid + i * 512;            // 0..4095 16B-chunks
                int row = idx >> 7, ch = idx & 127;
                unsigned dst = hA_u32 + (unsigned)(row * (SC_P * 4) + ch * 16);
                CP_ASYNC16(dst, src + row * 512 + ch * 4);
            }
            asm volatile("cp.async.commit_group;\n");
        }

        // prefetch gates_x while cp.async is in flight
        float gx0 = 0.f, gx1 = 0.f, gx2 = 0.f, gx3 = 0.f;
        if (tid < 256) {
            size_t gxo = (size_t)(row_global * NSEG + t) * G4 + j0 + jj;
            gx0 = __ldg(&g_gx[gxo]);
            gx1 = __ldg(&g_gx[gxo + 512]);
            gx2 = __ldg(&g_gx[gxo + 1024]);
            gx3 = __ldg(&g_gx[gxo + 1536]);
        }

        asm volatile("cp.async.wait_group 0;\n" ::: "memory");
        __syncthreads();

        // gates[32x32] partial over this warp's K slice
        float acc[4][4];
#pragma unroll
        for (int nt = 0; nt < 4; nt++)
#pragma unroll
            for (int i = 0; i < 4; i++) acc[nt][i] = 0.f;
#pragma unroll
        for (int ki = 0; ki < 8; ki++) {
            unsigned a0, a1, a2, a3;
            unsigned addr = ldbase + ki * 32;
            asm volatile("ldmatrix.sync.aligned.m8n8.x4.shared.b16 {%0,%1,%2,%3}, [%4];"
                         : "=r"(a0), "=r"(a1), "=r"(a2), "=r"(a3) : "r"(addr));
#pragma unroll
            for (int nt = 0; nt < 4; nt++)
                MMA_TF32(acc[nt], a0, a1, a2, a3, blo[nt][ki], bhi[nt][ki]);
        }
        {
            float* pb = pbuf + kq * (32 * 34);
            int row = mt * 16 + grp;
#pragma unroll
            for (int nt = 0; nt < 4; nt++) {
                int c0 = nt * 8 + tig * 2;
                pb[row * 34 + c0]           = acc[nt][0];
                pb[row * 34 + c0 + 1]       = acc[nt][1];
                pb[(row + 8) * 34 + c0]     = acc[nt][2];
                pb[(row + 8) * 34 + c0 + 1] = acc[nt][3];
            }
        }
        __syncthreads();

        if (tid < 256) {
            float gsum[4];
#pragma unroll
            for (int q = 0; q < 4; q++) {
                int col = q * 8 + jj;
                float s = 0.f;
#pragma unroll
                for (int k = 0; k < 8; k++) s += pbuf[k * (32 * 34) + b_hat * 34 + col];
                gsum[q] = s;
            }
            float gi = gsum[0] + gx0;
            float gf = gsum[1] + gx1;
            float gg = gsum[2] + gx2;
            float go = gsum[3] + gx3;
            c_st = sigmf(gf) * c_st + sigmf(gi) * tanhfast(gg);
            float h = sigmf(go) * tanhfast(c_st);
            ghw[(size_t)(t + 1) * Bb * H2 + (size_t)row_global * H2 + j0 + jj] = f2tf(h);
        }

        // release/acquire grid barrier (monotonic counter, no reset race)
        __syncthreads();
        if (tid == 0) {
            unsigned one = 1;
            asm volatile("red.release.gpu.global.add.u32 [%0], %1;"
                         :: "l"(pcount), "r"(one) : "memory");
            unsigned target = 128u * (unsigned)(t + 1);
            unsigned cur;
            do {
                asm volatile("ld.acquire.gpu.global.u32 %0, [%1];"
                             : "=r"(cur) : "l"(pcount));
            } while (cur < target);
        }
        __syncthreads();
    }
}

// ---------------- log_softmax + output permutation ----------------
__global__ void lsm_kernel(const float* __restrict__ logits, float* __restrict__ out)
{
    int r = blockIdx.x;              // t*64 + b
    int v = threadIdx.x;             // 64 threads
    float x = logits[(size_t)r * Tt + v];
    float m = x;
#pragma unroll
    for (int o = 16; o; o >>= 1) m = fmaxf(m, __shfl_xor_sync(0xffffffffu, m, o));
    __shared__ float s1[2], s2[2];
    if ((v & 31) == 0) s1[v >> 5] = m;
    __syncthreads();
    m = fmaxf(s1[0], s1[1]);
    float s = expf(x - m);
#pragma unroll
    for (int o = 16; o; o >>= 1) s += __shfl_xor_sync(0xffffffffu, s, o);
    if ((v & 31) == 0) s2[v >> 5] = s;
    __syncthreads();
    s = s2[0] + s2[1];
    int t = r >> 6, bb = r & 63;
    out[(size_t)(bb * NSEG + t) * Tt + v] = x - m - logf(s);
}

// ---------------- launcher ----------------
extern "C" void kernel_launch(void* const* d_in, const int* in_sizes, int n_in,
                              void* d_out, int out_size)
{
    const int*   word_ids = (const int*)d_in[0];
    const float* embed    = (const float*)d_in[1];
    const float* enc      = (const float*)d_in[2];
    const float* w1       = (const float*)d_in[3];
    const float* b1       = (const float*)d_in[4];
    const float* w2       = (const float*)d_in[5];
    const float* b2       = (const float*)d_in[6];
    const float* w3       = (const float*)d_in[7];
    const float* b3       = (const float*)d_in[8];
    const float* Wih      = (const float*)d_in[9];
    const float* Whh      = (const float*)d_in[10];
    const float* Wfc      = (const float*)d_in[11];
    float* out = (float*)d_out;

    void *pU, *pWall, *pDecin, *pGx, *pH, *pLog;
    cudaGetSymbolAddress(&pU, g_U);
    cudaGetSymbolAddress(&pWall, g_Wall);
    cudaGetSymbolAddress(&pDecin, g_decin);
    cudaGetSymbolAddress(&pGx, g_gx);
    cudaGetSymbolAddress(&pH, g_h);
    cudaGetSymbolAddress(&pLog, g_logits);

    cudaFuncSetAttribute(gemm3, cudaFuncAttributeMaxDynamicSharedMemorySize, GEMM3_SMEM);
    cudaFuncSetAttribute(gemm2, cudaFuncAttributeMaxDynamicSharedMemorySize, GEMM2_SMEM);
    cudaFuncSetAttribute(scan3, cudaFuncAttributeMaxDynamicSharedMemorySize, SCAN3_SMEM);

    pack_wall<<<768, 64>>>(w1, w2, w3);
    seg_feat<<<NSEGT, 256>>>(word_ids, embed, enc);

    // conv taps: U[65536,768] = gather(embed) @ Wall^T
    gemm3<<<dim3(768 / HBN, NROWS / HBM), 256, GEMM3_SMEM>>>(
        embed, (const float*)pWall, (float*)pU, NROWS, 768, Dd, word_ids);
    conv_reduce<<<NSEGT, 128>>>(b1, b2, b3);

    // gates_x[8192,2048] = dec_in @ W_ih^T
    gemm3<<<dim3(G4 / HBN, NSEGT / HBM), 256, GEMM3_SMEM>>>(
        (const float*)pDecin, Wih, (float*)pGx, NSEGT, G4, DIN, nullptr);

    h0_kernel<<<Bb, 256>>>(enc);

    scan3<<<128, 512, SCAN3_SMEM>>>(Whh);

    // logits[8192,64] = h(1..128) @ W_fc^T  (f2tf idempotent on tf32 bits)
    gemm2<<<dim3(Tt / GBN, NSEGT / GBM), 256, GEMM2_SMEM>>>(
        (const float*)pH + (size_t)Bb * H2, Wfc, (float*)pLog, NSEGT, Tt, H2);

    lsm_kernel<<<NSEGT, Tt>>>((const float*)pLog, out);
}

// round 4
// speedup vs baseline: 3.0655x; 1.2491x over previous
#include <cuda_runtime.h>
#include <cuda_bf16.h>
#include <math.h>

// ---------------- problem constants ----------------
#define Bb    64
#define Ss    1024
#define Dd    256
#define Hh    256
#define H2    512
#define Ff    128
#define Tt    64
#define Ll    8
#define NSEG  128
#define DIN   1152
#define G4    2048           // 4 * H2
#define NROWS 65536          // B * S
#define NSEGT 8192           // B * NSEG

// ---------------- scratch (static device, no allocs) ----------------
__device__ float g_decin[NSEGT * DIN];
__device__ float g_U[(size_t)NROWS * 768];
__device__ float g_Wall[768 * Dd];
__device__ float g_gx[(size_t)NSEGT * G4];
__device__ float g_h[(size_t)129 * Bb * H2];            // fp32 h (for logits GEMM)
__device__ __nv_bfloat16 g_hb[(size_t)129 * Bb * H2];   // bf16 h (for recurrence)
__device__ unsigned g_bar_count;

// ---------------- helpers ----------------
__device__ __forceinline__ float sigmf(float x) { return 1.f / (1.f + __expf(-x)); }
__device__ __forceinline__ float tanhfast(float x) { return 2.f / (1.f + __expf(-2.f * x)) - 1.f; }
__device__ __forceinline__ unsigned packbf(float lo, float hi) {
    unsigned d;
    asm("cvt.rn.bf16x2.f32 %0, %1, %2;" : "=r"(d) : "f"(hi), "f"(lo));
    return d;
}

#define MMA_TF32(acc, a0, a1, a2, a3, b0, b1)                                  \
    asm("mma.sync.aligned.m16n8k8.row.col.f32.tf32.tf32.f32 "                  \
        "{%0,%1,%2,%3},{%4,%5,%6,%7},{%8,%9},{%0,%1,%2,%3};"                   \
        : "+f"(acc[0]), "+f"(acc[1]), "+f"(acc[2]), "+f"(acc[3])               \
        : "r"(a0), "r"(a1), "r"(a2), "r"(a3), "r"(b0), "r"(b1))

#define MMA_BF16(acc, a0, a1, a2, a3, b0, b1)                                  \
    asm("mma.sync.aligned.m16n8k16.row.col.f32.bf16.bf16.f32 "                 \
        "{%0,%1,%2,%3},{%4,%5,%6,%7},{%8,%9},{%0,%1,%2,%3};"                   \
        : "+f"(acc[0]), "+f"(acc[1]), "+f"(acc[2]), "+f"(acc[3])               \
        : "r"(a0), "r"(a1), "r"(a2), "r"(a3), "r"(b0), "r"(b1))

#define LDSM_X4(r0, r1, r2, r3, addr)                                          \
    asm volatile("ldmatrix.sync.aligned.m8n8.x4.shared.b16 {%0,%1,%2,%3}, [%4];" \
                 : "=r"(r0), "=r"(r1), "=r"(r2), "=r"(r3) : "r"(addr))

#define CP_ASYNC16(dst, src)                                                   \
    asm volatile("cp.async.cg.shared.global [%0], [%1], 16;\n" ::              \
                 "r"(dst), "l"(src))

// ================= 128x128 double-buffered tf32 GEMM (LDSM, no CVT) =========
#define HBM 128
#define HBN 128
#define HBK 32
#define HSP 36
#define GEMM3_SMEM ((2 * HBM * HSP + 2 * HBN * HSP) * 4)   // 73728 B

__global__ __launch_bounds__(256, 2) void gemm3(
    const float* __restrict__ A, const float* __restrict__ Bw,
    float* __restrict__ C, int M, int N, int K,
    const int* __restrict__ gather)
{
    extern __shared__ unsigned gsm[];
    unsigned* AsAll = gsm;
    unsigned* BsAll = gsm + 2 * HBM * HSP;
    __shared__ int rows_s[HBM];

    int tid = threadIdx.x;
    int mBase = blockIdx.y * HBM, nBase = blockIdx.x * HBN;
    if (tid < HBM) rows_s[tid] = gather ? gather[mBase + tid] : (mBase + tid);
    __syncthreads();

    int w = tid >> 5, lane = tid & 31;
    int grp = lane >> 2, tig = lane & 3;
    int wm = w & 1, wn = w >> 1;    // 2x4 warp grid, warp tile 64x32

    unsigned asmem = (unsigned)__cvta_generic_to_shared(AsAll);
    unsigned bsmem = (unsigned)__cvta_generic_to_shared(BsAll);
    // per-thread invariant ldsm address parts
    unsigned aAddr0 = asmem + (unsigned)((wm * 64 + (lane & 15)) * (HSP * 4) + ((lane >> 4) << 4));
    unsigned bAddr0 = bsmem + (unsigned)((wn * 32 + ((lane >> 4) << 3) + (lane & 7)) * (HSP * 4)
                                         + (((lane >> 3) & 1) << 4));

    float acc[4][4][4];
#pragma unroll
    for (int mt = 0; mt < 4; mt++)
#pragma unroll
        for (int nt = 0; nt < 4; nt++)
#pragma unroll
            for (int i = 0; i < 4; i++) acc[mt][nt][i] = 0.f;

    int nkt = K / HBK;

#define GLOAD3(s, kt) do {                                                      \
        int koff = (kt) * HBK;                                                  \
        _Pragma("unroll")                                                       \
        for (int i = 0; i < 4; i++) {                                           \
            int cid = tid + i * 256;                                            \
            int row = cid >> 3, ch = (cid & 7) * 4;                             \
            const float* src = A + (size_t)rows_s[row] * K + koff + ch;         \
            unsigned dst = (unsigned)__cvta_generic_to_shared(                  \
                &AsAll[(s) * HBM * HSP + row * HSP + ch]);                      \
            CP_ASYNC16(dst, src);                                               \
        }                                                                       \
        _Pragma("unroll")                                                       \
        for (int i = 0; i < 4; i++) {                                           \
            int cid = tid + i * 256;                                            \
            int row = cid >> 3, ch = (cid & 7) * 4;                             \
            const float* src = Bw + (size_t)(nBase + row) * K + koff + ch;      \
            unsigned dst = (unsigned)__cvta_generic_to_shared(                  \
                &BsAll[(s) * HBN * HSP + row * HSP + ch]);                      \
            CP_ASYNC16(dst, src);                                               \
        }                                                                       \
        asm volatile("cp.async.commit_group;\n");                               \
    } while (0)

    GLOAD3(0, 0);

    for (int kt = 0; kt < nkt; kt++) {
        int s = kt & 1;
        if (kt + 1 < nkt) {
            GLOAD3((kt + 1) & 1, kt + 1);
            asm volatile("cp.async.wait_group 1;\n" ::: "memory");
        } else {
            asm volatile("cp.async.wait_group 0;\n" ::: "memory");
        }
        __syncthreads();

        unsigned aS = aAddr0 + (unsigned)(s * HBM * HSP * 4);
        unsigned bS = bAddr0 + (unsigned)(s * HBN * HSP * 4);
#pragma unroll
        for (int ks = 0; ks < 4; ks++) {
            unsigned kb = ks * 32;   // k0*4 bytes
            unsigned bfr[2][4];
#pragma unroll
            for (int ntp = 0; ntp < 2; ntp++)
                LDSM_X4(bfr[ntp][0], bfr[ntp][1], bfr[ntp][2], bfr[ntp][3],
                        bS + ntp * (16 * HSP * 4) + kb);
#pragma unroll
            for (int mt = 0; mt < 4; mt++) {
                unsigned a0, a1, a2, a3;
                LDSM_X4(a0, a1, a2, a3, aS + mt * (16 * HSP * 4) + kb);
                MMA_TF32(acc[mt][0], a0, a1, a2, a3, bfr[0][0], bfr[0][1]);
                MMA_TF32(acc[mt][1], a0, a1, a2, a3, bfr[0][2], bfr[0][3]);
                MMA_TF32(acc[mt][2], a0, a1, a2, a3, bfr[1][0], bfr[1][1]);
                MMA_TF32(acc[mt][3], a0, a1, a2, a3, bfr[1][2], bfr[1][3]);
            }
        }
        __syncthreads();
    }

#pragma unroll
    for (int mt = 0; mt < 4; mt++) {
        int row0 = mBase + wm * 64 + mt * 16 + grp;
#pragma unroll
        for (int nt = 0; nt < 4; nt++) {
            int col = nBase + wn * 32 + nt * 8 + tig * 2;
            *(float2*)&C[(size_t)row0 * N + col] = make_float2(acc[mt][nt][0], acc[mt][nt][1]);
            *(float2*)&C[(size_t)(row0 + 8) * N + col] = make_float2(acc[mt][nt][2], acc[mt][nt][3]);
        }
    }
}

// ================= 128x64 GEMM (logits) — LDSM, no CVT =================
#define GBM 128
#define GBN 64
#define GSP 36
#define GEMM2_SMEM ((2 * GBM * GSP + 2 * GBN * GSP) * 4)   // 55296 B

__global__ __launch_bounds__(256, 2) void gemm2(
    const float* __restrict__ A, const float* __restrict__ Bw,
    float* __restrict__ C, int M, int N, int K)
{
    extern __shared__ unsigned gsm[];
    unsigned* AsAll = gsm;
    unsigned* BsAll = gsm + 2 * GBM * GSP;

    int tid = threadIdx.x;
    int mBase = blockIdx.y * GBM, nBase = blockIdx.x * GBN;

    int w = tid >> 5, lane = tid & 31;
    int grp = lane >> 2, tig = lane & 3;
    int wm = w & 3, wn = w >> 2;    // 4x2, warp tile 32x32

    unsigned asmem = (unsigned)__cvta_generic_to_shared(AsAll);
    unsigned bsmem = (unsigned)__cvta_generic_to_shared(BsAll);
    unsigned aAddr0 = asmem + (unsigned)((wm * 32 + (lane & 15)) * (GSP * 4) + ((lane >> 4) << 4));
    unsigned bAddr0 = bsmem + (unsigned)((wn * 32 + ((lane >> 4) << 3) + (lane & 7)) * (GSP * 4)
                                         + (((lane >> 3) & 1) << 4));

    float acc[2][4][4];
#pragma unroll
    for (int mt = 0; mt < 2; mt++)
#pragma unroll
        for (int nt = 0; nt < 4; nt++)
#pragma unroll
            for (int i = 0; i < 4; i++) acc[mt][nt][i] = 0.f;

    int nkt = K / HBK;

#define GLOAD2(s, kt) do {                                                      \
        int koff = (kt) * HBK;                                                  \
        _Pragma("unroll")                                                       \
        for (int i = 0; i < 4; i++) {                                           \
            int cid = tid + i * 256;                                            \
            int row = cid >> 3, ch = (cid & 7) * 4;                             \
            const float* src = A + (size_t)(mBase + row) * K + koff + ch;       \
            unsigned dst = (unsigned)__cvta_generic_to_shared(                  \
                &AsAll[(s) * GBM * GSP + row * GSP + ch]);                      \
            CP_ASYNC16(dst, src);                                               \
        }                                                                       \
        _Pragma("unroll")                                                       \
        for (int i = 0; i < 2; i++) {                                           \
            int cid = tid + i * 256;                                            \
            int row = cid >> 3, ch = (cid & 7) * 4;                             \
            const float* src = Bw + (size_t)(nBase + row) * K + koff + ch;      \
            unsigned dst = (unsigned)__cvta_generic_to_shared(                  \
                &BsAll[(s) * GBN * GSP + row * GSP + ch]);                      \
            CP_ASYNC16(dst, src);                                               \
        }                                                                       \
        asm volatile("cp.async.commit_group;\n");                               \
    } while (0)

    GLOAD2(0, 0);

    for (int kt = 0; kt < nkt; kt++) {
        int s = kt & 1;
        if (kt + 1 < nkt) {
            GLOAD2((kt + 1) & 1, kt + 1);
            asm volatile("cp.async.wait_group 1;\n" ::: "memory");
        } else {
            asm volatile("cp.async.wait_group 0;\n" ::: "memory");
        }
        __syncthreads();

        unsigned aS = aAddr0 + (unsigned)(s * GBM * GSP * 4);
        unsigned bS = bAddr0 + (unsigned)(s * GBN * GSP * 4);
#pragma unroll
        for (int ks = 0; ks < 4; ks++) {
            unsigned kb = ks * 32;
            unsigned bfr[2][4];
#pragma unroll
            for (int ntp = 0; ntp < 2; ntp++)
                LDSM_X4(bfr[ntp][0], bfr[ntp][1], bfr[ntp][2], bfr[ntp][3],
                        bS + ntp * (16 * GSP * 4) + kb);
#pragma unroll
            for (int mt = 0; mt < 2; mt++) {
                unsigned a0, a1, a2, a3;
                LDSM_X4(a0, a1, a2, a3, aS + mt * (16 * GSP * 4) + kb);
                MMA_TF32(acc[mt][0], a0, a1, a2, a3, bfr[0][0], bfr[0][1]);
                MMA_TF32(acc[mt][1], a0, a1, a2, a3, bfr[0][2], bfr[0][3]);
                MMA_TF32(acc[mt][2], a0, a1, a2, a3, bfr[1][0], bfr[1][1]);
                MMA_TF32(acc[mt][3], a0, a1, a2, a3, bfr[1][2], bfr[1][3]);
            }
        }
        __syncthreads();
    }

#pragma unroll
    for (int mt = 0; mt < 2; mt++) {
        int row0 = mBase + wm * 32 + mt * 16 + grp;
#pragma unroll
        for (int nt = 0; nt < 4; nt++) {
            int col = nBase + wn * 32 + nt * 8 + tig * 2;
            *(float2*)&C[(size_t)row0 * N + col] = make_float2(acc[mt][nt][0], acc[mt][nt][1]);
            *(float2*)&C[(size_t)(row0 + 8) * N + col] = make_float2(acc[mt][nt][2], acc[mt][nt][3]);
        }
    }
}

// ---------------- pack conv weights into [768,256] ----------------
__global__ void pack_wall(const float* __restrict__ w1, const float* __restrict__ w2,
                          const float* __restrict__ w3)
{
    int n = blockIdx.x, k4 = threadIdx.x;
    const float* src;
    if (n < 128)       src = w1 + n * Dd;
    else if (n < 384) { int m = n - 128; src = w2 + ((m & 127) * 2 + (m >> 7)) * Dd; }
    else              { int m = n - 384; src = w3 + ((m & 127) * 3 + (m >> 7)) * Dd; }
    ((float4*)(g_Wall + n * Dd))[k4] = ((const float4*)src)[k4];
}

// ---------------- segment features ----------------
__global__ __launch_bounds__(256) void seg_feat(
    const int* __restrict__ word_ids, const float* __restrict__ embed,
    const float* __restrict__ enc)
{
    int r = blockIdx.x;
    int b = r >> 7, seg = r & 127;
    __shared__ int ids[8];
    int tid = threadIdx.x;
    if (tid < 8) ids[tid] = word_ids[b * Ss + seg * Ll + tid];
    __syncthreads();
    {
        float s = 0.f;
#pragma unroll
        for (int t = 0; t < 8; t++) s += embed[(size_t)ids[t] * Dd + tid];
        g_decin[(size_t)r * DIN + tid] = s * 0.125f;
    }
    for (int k = tid; k < H2; k += 256) {
        float s = 0.f;
#pragma unroll
        for (int t = 0; t < 8; t++) s += enc[(size_t)(b * Ss + seg * Ll + t) * H2 + k];
        g_decin[(size_t)r * DIN + Dd + k] = s * 0.125f;
    }
}

// ---------------- conv tap-sum + relu + maxpool ----------------
__global__ __launch_bounds__(128) void conv_reduce(
    const float* __restrict__ b1, const float* __restrict__ b2, const float* __restrict__ b3)
{
    int r = blockIdx.x, f = threadIdx.x;
    const float* U = g_U + (size_t)r * 8 * 768;
    float m1 = -1e30f, m2 = -1e30f, m3 = -1e30f;
#pragma unroll
    for (int t = 0; t < 8; t++) m1 = fmaxf(m1, U[t * 768 + f]);
#pragma unroll
    for (int t = 0; t < 7; t++) m2 = fmaxf(m2, U[t * 768 + 128 + f] + U[(t + 1) * 768 + 256 + f]);
#pragma unroll
    for (int t = 0; t < 6; t++)
        m3 = fmaxf(m3, U[t * 768 + 384 + f] + U[(t + 1) * 768 + 512 + f] + U[(t + 2) * 768 + 640 + f]);
    float* d = g_decin + (size_t)r * DIN + 768;
    d[f]       = fmaxf(m1 + b1[f], 0.f);
    d[128 + f] = fmaxf(m2 + b2[f], 0.f);
    d[256 + f] = fmaxf(m3 + b3[f], 0.f);
}

// ---------------- h0 (bf16) + barrier reset ----------------
__global__ void h0_kernel(const float* __restrict__ enc)
{
    if (blockIdx.x == 0 && threadIdx.x == 0) g_bar_count = 0;
    int b = blockIdx.x;
    for (int j = threadIdx.x; j < H2; j += blockDim.x) {
        float v = (j < Hh) ? enc[(size_t)(b * Ss + Ss - 1) * H2 + j]
                           : enc[(size_t)(b * Ss) * H2 + j];
        g_hb[(size_t)b * H2 + j] = __float2bfloat16(v);
    }
}

// ================= bf16 tensor-core LSTM scan =================
// 128 CTAs = 64 col-groups (8 hidden units) x 2 batch-groups (32 rows).
// W_hh bf16 fragments in registers. h in gmem as bf16; each warp cp.asyncs
// ONLY its own 16-row x 64-col slice (2KB) -> per-warp wait, no CTA sync.
#define SCP 520    // bf16 pitch (1040B rows, 16B aligned)
#define SCAN4_SMEM (32 * SCP * 2 + 8 * 32 * 34 * 4)   // 33280 + 34816 = 68096 B

__global__ __launch_bounds__(512, 1) void scan4(const float* __restrict__ Whh)
{
    extern __shared__ unsigned ssm[];
    __nv_bfloat16* hA = (__nv_bfloat16*)ssm;                 // [32][520]
    float* pbuf = (float*)((char*)ssm + 32 * SCP * 2);       // [8][32][34]

    int tid = threadIdx.x;
    int lane = tid & 31, w = tid >> 5;
    int grp = lane >> 2, tig = lane & 3;
    int mt = w & 1;          // rows mt*16..+15 (within 32)
    int kq = w >> 1;         // 0..7: k cols kq*64..+63
    int cid = blockIdx.x;
    int bg = cid & 1;
    int j0 = (cid >> 1) * 8;

    // W_hh bf16 fragments: gate nt, unit grp, k chunk kc (16 wide)
    unsigned bw[4][4][2];
#pragma unroll
    for (int nt = 0; nt < 4; nt++) {
        const float* wr = Whh + (size_t)(nt * H2 + j0 + grp) * H2 + kq * 64;
#pragma unroll
        for (int kc = 0; kc < 4; kc++) {
            const float* p = wr + kc * 16 + tig * 2;
            bw[nt][kc][0] = packbf(p[0], p[1]);
            bw[nt][kc][1] = packbf(p[8], p[9]);
        }
    }

    const __nv_bfloat16* ghb = g_hb;
    unsigned* pcount = &g_bar_count;

    float c_st = 0.f;
    int b_hat = tid >> 3, jj = tid & 7;     // epilogue item (tid<256)
    int row_global = bg * 32 + b_hat;

    unsigned hA_u32 = (unsigned)__cvta_generic_to_shared(hA);
    // staging dst base for this warp's slice
    unsigned dstbase = hA_u32 + (unsigned)((mt * 16) * (SCP * 2) + kq * 128);
    // ldmatrix base: row mt*16+(lane&15), byte col kq*128 + half-select
    unsigned ldbase = hA_u32 + (unsigned)((mt * 16 + (lane & 15)) * (SCP * 2)
                                          + kq * 128 + ((lane >> 4) << 4));

    for (int t = 0; t < NSEG; t++) {
        // per-warp staging: 16 rows x 128B = 4 cp.async per lane
        {
            const __nv_bfloat16* src = ghb + (size_t)t * Bb * H2
                                     + (size_t)(bg * 32 + mt * 16) * H2 + kq * 64;
#pragma unroll
            for (int i = 0; i < 4; i++) {
                int c = lane + 32 * i;
                int r = c >> 3, ch = c & 7;
                CP_ASYNC16(dstbase + (unsigned)(r * (SCP * 2) + ch * 16),
                           src + r * H2 + ch * 8);
            }
            asm volatile("cp.async.commit_group;\n");
        }

        // prefetch gates_x while copies are in flight
        float gx0 = 0.f, gx1 = 0.f, gx2 = 0.f, gx3 = 0.f;
        if (tid < 256) {
            size_t gxo = (size_t)(row_global * NSEG + t) * G4 + j0 + jj;
            gx0 = __ldg(&g_gx[gxo]);
            gx1 = __ldg(&g_gx[gxo + 512]);
            gx2 = __ldg(&g_gx[gxo + 1024]);
            gx3 = __ldg(&g_gx[gxo + 1536]);
        }

        asm volatile("cp.async.wait_group 0;\n" ::: "memory");
        __syncwarp();

        // [32 x 32] gate partial over this warp's K slice: 4 ldsm + 16 mma
        float acc[4][4];
#pragma unroll
        for (int nt = 0; nt < 4; nt++)
#pragma unroll
            for (int i = 0; i < 4; i++) acc[nt][i] = 0.f;
#pragma unroll
        for (int kc = 0; kc < 4; kc++) {
            unsigned a0, a1, a2, a3;
            LDSM_X4(a0, a1, a2, a3, ldbase + kc * 32);
#pragma unroll
            for (int nt = 0; nt < 4; nt++)
                MMA_BF16(acc[nt], a0, a1, a2, a3, bw[nt][kc][0], bw[nt][kc][1]);
        }
        {
            float* pb = pbuf + kq * (32 * 34);
            int row = mt * 16 + grp;
#pragma unroll
            for (int nt = 0; nt < 4; nt++) {
                int c0 = nt * 8 + tig * 2;
                pb[row * 34 + c0]           = acc[nt][0];
                pb[row * 34 + c0 + 1]       = acc[nt][1];
                pb[(row + 8) * 34 + c0]     = acc[nt][2];
                pb[(row + 8) * 34 + c0 + 1] = acc[nt][3];
            }
        }
        __syncthreads();

        if (tid < 256) {
            float gsum[4];
#pragma unroll
            for (int q = 0; q < 4; q++) {
                int col = q * 8 + jj;
                float s = 0.f;
#pragma unroll
                for (int k = 0; k < 8; k++) s += pbuf[k * (32 * 34) + b_hat * 34 + col];
                gsum[q] = s;
            }
            float gi = gsum[0] + gx0;
            float gf = gsum[1] + gx1;
            float gg = gsum[2] + gx2;
            float go = gsum[3] + gx3;
            c_st = sigmf(gf) * c_st + sigmf(gi) * tanhfast(gg);
            float h = sigmf(go) * tanhfast(c_st);
            size_t ho = (size_t)(t + 1) * Bb * H2 + (size_t)row_global * H2 + j0 + jj;
            g_hb[ho] = __float2bfloat16(h);   // recurrence copy
            g_h[ho] = h;                      // fp32 copy for logits GEMM
        }

        // release/acquire grid barrier (monotonic counter)
        __syncthreads();
        if (tid == 0) {
            unsigned one = 1;
            asm volatile("red.release.gpu.global.add.u32 [%0], %1;"
                         :: "l"(pcount), "r"(one) : "memory");
            unsigned target = 128u * (unsigned)(t + 1);
            unsigned cur;
            do {
                asm volatile("ld.acquire.gpu.global.u32 %0, [%1];"
                             : "=r"(cur) : "l"(pcount));
            } while (cur < target);
        }
        __syncthreads();
    }
}

// ---------------- log_softmax + output permutation ----------------
__global__ void lsm_kernel(const float* __restrict__ logits, float* __restrict__ out)
{
    int r = blockIdx.x;              // t*64 + b
    int v = threadIdx.x;             // 64 threads
    float x = logits[(size_t)r * Tt + v];
    float m = x;
#pragma unroll
    for (int o = 16; o; o >>= 1) m = fmaxf(m, __shfl_xor_sync(0xffffffffu, m, o));
    __shared__ float s1[2], s2[2];
    if ((v & 31) == 0) s1[v >> 5] = m;
    __syncthreads();
    m = fmaxf(s1[0], s1[1]);
    float s = expf(x - m);
#pragma unroll
    for (int o = 16; o; o >>= 1) s += __shfl_xor_sync(0xffffffffu, s, o);
    if ((v & 31) == 0) s2[v >> 5] = s;
    __syncthreads();
    s = s2[0] + s2[1];
    int t = r >> 6, bb = r & 63;
    out[(size_t)(bb * NSEG + t) * Tt + v] = x - m - logf(s);
}

// ---------------- launcher ----------------
extern "C" void kernel_launch(void* const* d_in, const int* in_sizes, int n_in,
                              void* d_out, int out_size)
{
    const int*   word_ids = (const int*)d_in[0];
    const float* embed    = (const float*)d_in[1];
    const float* enc      = (const float*)d_in[2];
    const float* w1       = (const float*)d_in[3];
    const float* b1       = (const float*)d_in[4];
    const float* w2       = (const float*)d_in[5];
    const float* b2       = (const float*)d_in[6];
    const float* w3       = (const float*)d_in[7];
    const float* b3       = (const float*)d_in[8];
    const float* Wih      = (const float*)d_in[9];
    const float* Whh      = (const float*)d_in[10];
    const float* Wfc      = (const float*)d_in[11];
    float* out = (float*)d_out;

    void *pU, *pWall, *pDecin, *pGx, *pH, *pLog;
    cudaGetSymbolAddress(&pU, g_U);
    cudaGetSymbolAddress(&pWall, g_Wall);
    cudaGetSymbolAddress(&pDecin, g_decin);
    cudaGetSymbolAddress(&pGx, g_gx);
    cudaGetSymbolAddress(&pH, g_h);
    pLog = pU;   // reuse g_U for logits scratch (U dead after conv_reduce)

    cudaFuncSetAttribute(gemm3, cudaFuncAttributeMaxDynamicSharedMemorySize, GEMM3_SMEM);
    cudaFuncSetAttribute(gemm2, cudaFuncAttributeMaxDynamicSharedMemorySize, GEMM2_SMEM);
    cudaFuncSetAttribute(scan4, cudaFuncAttributeMaxDynamicSharedMemorySize, SCAN4_SMEM);

    pack_wall<<<768, 64>>>(w1, w2, w3);
    seg_feat<<<NSEGT, 256>>>(word_ids, embed, enc);

    // conv taps: U[65536,768] = gather(embed) @ Wall^T
    gemm3<<<dim3(768 / HBN, NROWS / HBM), 256, GEMM3_SMEM>>>(
        embed, (const float*)pWall, (float*)pU, NROWS, 768, Dd, word_ids);
    conv_reduce<<<NSEGT, 128>>>(b1, b2, b3);

    // gates_x[8192,2048] = dec_in @ W_ih^T
    gemm3<<<dim3(G4 / HBN, NSEGT / HBM), 256, GEMM3_SMEM>>>(
        (const float*)pDecin, Wih, (float*)pGx, NSEGT, G4, DIN, nullptr);

    h0_kernel<<<Bb, 256>>>(enc);

    scan4<<<128, 512, SCAN4_SMEM>>>(Whh);

    // logits[8192,64] = h(1..128) @ W_fc^T
    gemm2<<<dim3(Tt / GBN, NSEGT / GBM), 256, GEMM2_SMEM>>>(
        (const float*)pH + (size_t)Bb * H2, Wfc, (float*)pLog, NSEGT, Tt, H2);

    lsm_kernel<<<NSEGT, Tt>>>((const float*)pLog, out);
}